// round 7
// baseline (speedup 1.0000x reference)
#include <cuda_runtime.h>
#include <cuda_bf16.h>
#include <cstdint>

typedef unsigned long long ull;

// Problem constants
#define BB 2
#define MM 4096
#define CC 256
#define HH 64
#define WW 64
#define NLVL 4
#define RAD 4
#define SIDE 9
#define OUTCH (NLVL * SIDE * SIDE)   // 324

// Pyramid (pixel-major: [b][level][y][x][c]) in float
#define OFF0 0
#define OFF1 (4096 * 256)
#define OFF2 ((4096 + 1024) * 256)
#define OFF3 ((4096 + 1024 + 256) * 256)
#define BSTR ((4096 + 1024 + 256 + 64) * 256)
#define PYR_TOTAL (BB * BSTR)

__device__ float4 g_pyr4[PYR_TOTAL / 4];     // 11.1 MB static scratch
__device__ int g_binCnt[512];
__device__ int g_binStart[512];
__device__ int g_perm[BB * MM];              // sorted position -> point id
__device__ int g_ipos[BB * MM];              // point id -> sorted position
__device__ float g_tmp[BB * MM * OUTCH];     // staged output, [pos][324]

// ---------------------------------------------------------------------------
// packed f32x2 helpers
// ---------------------------------------------------------------------------
__device__ __forceinline__ ull pk(float x, float y) {
    ull r;
    asm("mov.b64 %0, {%1, %2};" : "=l"(r) : "f"(x), "f"(y));
    return r;
}
__device__ __forceinline__ float2 upk(ull v) {
    float2 f;
    asm("mov.b64 {%0, %1}, %2;" : "=f"(f.x), "=f"(f.y) : "l"(v));
    return f;
}
__device__ __forceinline__ void ffma2(ull& acc, ull a, ull b) {
    asm("fma.rn.f32x2 %0, %1, %2, %3;" : "=l"(acc) : "l"(a), "l"(b), "l"(acc));
}

// ---------------------------------------------------------------------------
// Kernel A1: transpose fmap2 (b, c, p) -> pyramid level 0 (b, p, c)
// ---------------------------------------------------------------------------
__global__ void transpose_l0_kernel(const float* __restrict__ fmap2) {
    __shared__ float tile[32][33];
    float* g = reinterpret_cast<float*>(g_pyr4);
    int b  = blockIdx.z;
    int c0 = blockIdx.y * 32;
    int p0 = blockIdx.x * 32;
    const float* in_b = fmap2 + (size_t)b * CC * (HH * WW);
    #pragma unroll
    for (int r = threadIdx.y; r < 32; r += 8)
        tile[r][threadIdx.x] = in_b[(size_t)(c0 + r) * (HH * WW) + p0 + threadIdx.x];
    __syncthreads();
    float* out_b = g + (size_t)b * BSTR;
    #pragma unroll
    for (int r = threadIdx.y; r < 32; r += 8)
        out_b[(size_t)(p0 + r) * CC + c0 + threadIdx.x] = tile[threadIdx.x][r];
}

// ---------------------------------------------------------------------------
// Kernel A2 (fused): levels 1..3 pooled directly from level 0 (one launch).
// avg of 2^l x 2^l block == iterated 2x2 means (up to fp rounding).
// ---------------------------------------------------------------------------
__global__ void pool_fused_kernel() {
    float* g = reinterpret_cast<float*>(g_pyr4);
    const int n1 = BB * 32 * 32 * CC;
    const int n2 = BB * 16 * 16 * CC;
    const int n3 = BB * 8 * 8 * CC;
    int tid = blockIdx.x * blockDim.x + threadIdx.x;
    int Wo, k, off, local;
    float inv;
    if (tid < n1)            { Wo = 32; k = 2; off = OFF1; local = tid;          inv = 0.25f; }
    else if (tid < n1 + n2)  { Wo = 16; k = 4; off = OFF2; local = tid - n1;     inv = 1.f / 16.f; }
    else if (tid < n1+n2+n3) { Wo = 8;  k = 8; off = OFF3; local = tid - n1 - n2; inv = 1.f / 64.f; }
    else return;
    int c = local & (CC - 1);
    int idx = local >> 8;
    int x = idx % Wo; idx /= Wo;
    int y = idx % Wo; idx /= Wo;
    int b = idx;
    const float* ib = g + (size_t)b * BSTR;   // level 0
    float s = 0.0f;
    for (int dy = 0; dy < k; dy++)
        for (int dx = 0; dx < k; dx++)
            s += ib[((size_t)(y * k + dy) * WW + (x * k + dx)) * CC + c];
    g[(size_t)b * BSTR + off + ((size_t)y * Wo + x) * CC + c] = s * inv;
}

// ---------------------------------------------------------------------------
// Kernel S: single-block counting sort of points into 4x4-pixel bins
// (16x16 bins per batch -> 512 bins). Publishes g_binStart/g_binCnt,
// g_perm (pos->pt) and g_ipos (pt->pos).
// ---------------------------------------------------------------------------
__global__ void sort_kernel(const float* __restrict__ cents) {
    __shared__ int cnt[512];
    __shared__ int off[512];
    __shared__ int s[512];
    const int t = threadIdx.x;          // 1024 threads
    if (t < 512) cnt[t] = 0;
    __syncthreads();
    int mybin[8];
    #pragma unroll
    for (int i = 0; i < 8; i++) {
        int pt = t + i * 1024;
        float cx = cents[(size_t)pt * 2 + 0];
        float cy = cents[(size_t)pt * 2 + 1];
        int bx = min(15, ((int)cx) >> 2);
        int by = min(15, ((int)cy) >> 2);
        int bin = ((pt >> 12) << 8) | (by << 4) | bx;
        mybin[i] = bin;
        atomicAdd(&cnt[bin], 1);
    }
    __syncthreads();
    if (t < 512) s[t] = cnt[t];
    __syncthreads();
    #pragma unroll
    for (int d = 1; d < 512; d <<= 1) {
        int add = 0;
        if (t < 512 && t >= d) add = s[t - d];
        __syncthreads();
        if (t < 512) s[t] += add;
        __syncthreads();
    }
    if (t < 512) {
        int st = s[t] - cnt[t];
        off[t] = st;
        g_binStart[t] = st;
        g_binCnt[t] = cnt[t];
    }
    __syncthreads();
    #pragma unroll
    for (int i = 0; i < 8; i++) {
        int pt = t + i * 1024;
        int pos = atomicAdd(&off[mybin[i]], 1);
        g_perm[pos] = pt;
        g_ipos[pt] = pos;
    }
}

// ---------------------------------------------------------------------------
// Kernel B: one block per bin, one warp per group of 4 points of that bin.
// The 4 points share a superset lattice window per level (13/11/10/10 square)
// so each pixel vector is loaded ONCE and dotted against 4 queries
// (3.3x fewer LDG than warp-per-point). Lane owns 8 channels.
// ---------------------------------------------------------------------------
__global__ void __launch_bounds__(256)
sample_kernel(const float* __restrict__ fmap1,
              const float* __restrict__ cents,
              float* __restrict__ tmp) {
    __shared__ float Cs[8][4][100];
    const int bin = blockIdx.x;
    const int cnt = g_binCnt[bin];
    if (cnt == 0) return;
    const int start = g_binStart[bin];
    const int b  = bin >> 8;
    const int bx = bin & 15, by = (bin >> 4) & 15;
    const int warp = threadIdx.x >> 5;
    const int lane = threadIdx.x & 31;
    const float* pyr = reinterpret_cast<const float*>(g_pyr4) + (size_t)b * BSTR;

    const int lvlOff[4] = {OFF0, OFF1, OFF2, OFF3};
    const int lvlW[4]   = {64, 32, 16, 8};
    const int lvlS[4]   = {13, 11, 10, 10};

    const int nIter = (cnt + 31) >> 5;     // uniform across block
    for (int it = 0; it < nIter; it++) {
        const int g0 = start + it * 32 + warp * 4;
        const int rem = start + cnt - g0;
        const bool active = rem > 0;
        int npts = 0;
        float cxr[4], cyr[4];
        ull qA[4], qB[4], qC[4], qD[4];
        if (active) {
            npts = min(4, rem);
            #pragma unroll
            for (int i = 0; i < 4; i++) {
                const int pt = g_perm[g0 + (i < npts ? i : 0)];
                const float4* qp = reinterpret_cast<const float4*>(fmap1 + (size_t)pt * CC);
                const float4 q0 = qp[lane];
                const float4 q1 = qp[lane + 32];
                qA[i] = pk(q0.x, q0.y); qB[i] = pk(q0.z, q0.w);
                qC[i] = pk(q1.x, q1.y); qD[i] = pk(q1.z, q1.w);
                cxr[i] = cents[(size_t)pt * 2 + 0];
                cyr[i] = cents[(size_t)pt * 2 + 1];
            }
        }

        for (int lvl = 0; lvl < NLVL; lvl++) {
            __syncthreads();               // lockstep warps on the shared bin patch
            if (!active) continue;

            const int W = lvlW[lvl], S = lvlS[lvl];
            const int sx0 = ((bx << 2) >> lvl) - 4;
            const int sy0 = ((by << 2) >> lvl) - 4;
            const float sc = 1.0f / (float)(1 << lvl);

            float wx0r[4], wx1r[4], wy0r[4], wy1r[4];
            int ox[4], oy[4];
            #pragma unroll
            for (int i = 0; i < 4; i++) {
                const float cxl = cxr[i] * sc, cyl = cyr[i] * sc;
                const float fx = floorf(cxl), fy = floorf(cyl);
                wx1r[i] = cxl - fx; wx0r[i] = 1.0f - wx1r[i];
                wy1r[i] = cyl - fy; wy0r[i] = 1.0f - wy1r[i];
                ox[i] = (int)fx - 4 - sx0;     // in [0, S-10]
                oy[i] = (int)fy - 4 - sy0;
            }
            // this lane's designated point for the reduce-store (lanes 0,8,16,24)
            const int k8 = lane >> 3;
            const int oxk = k8 == 0 ? ox[0] : k8 == 1 ? ox[1] : k8 == 2 ? ox[2] : ox[3];
            const int oyk = k8 == 0 ? oy[0] : k8 == 1 ? oy[1] : k8 == 2 ? oy[2] : oy[3];

            const float4* base4 = reinterpret_cast<const float4*>(pyr + lvlOff[lvl]);
            const int npix = S * S;
            int u = 0, vv = 0;
            #pragma unroll 2
            for (int p = 0; p < npix; p++) {
                const int x = sx0 + u, y = sy0 + vv;
                const bool ok = ((unsigned)x < (unsigned)W) & ((unsigned)y < (unsigned)W);
                float s0 = 0.f, s1 = 0.f, s2 = 0.f, s3 = 0.f;
                if (ok) {
                    const float4* f = base4 + (size_t)(y * W + x) * 64;
                    const float4 A  = f[lane];
                    const float4 Bv = f[lane + 32];
                    const ull pA = pk(A.x, A.y),   pB = pk(A.z, A.w);
                    const ull pC = pk(Bv.x, Bv.y), pD = pk(Bv.z, Bv.w);
                    ull a0 = pk(0.f, 0.f), a1 = a0, a2 = a0, a3 = a0;
                    ffma2(a0, pA, qA[0]); ffma2(a0, pB, qB[0]); ffma2(a0, pC, qC[0]); ffma2(a0, pD, qD[0]);
                    ffma2(a1, pA, qA[1]); ffma2(a1, pB, qB[1]); ffma2(a1, pC, qC[1]); ffma2(a1, pD, qD[1]);
                    ffma2(a2, pA, qA[2]); ffma2(a2, pB, qB[2]); ffma2(a2, pC, qC[2]); ffma2(a2, pD, qD[2]);
                    ffma2(a3, pA, qA[3]); ffma2(a3, pB, qB[3]); ffma2(a3, pC, qC[3]); ffma2(a3, pD, qD[3]);
                    float2 t0 = upk(a0); s0 = t0.x + t0.y;
                    float2 t1 = upk(a1); s1 = t1.x + t1.y;
                    float2 t2 = upk(a2); s2 = t2.x + t2.y;
                    float2 t3 = upk(a3); s3 = t3.x + t3.y;
                }
                // 4-value cross-warp reduction:
                //   lanes 0-7 -> s0, 8-15 -> s1, 16-23 -> s2, 24-31 -> s3
                const unsigned full = 0xffffffffu;
                const bool hi16 = (lane & 16) != 0;
                const bool hi8  = (lane & 8) != 0;
                float rA = __shfl_xor_sync(full, hi16 ? s0 : s2, 16);
                float u2 = (hi16 ? s2 : s0) + rA;
                float rB = __shfl_xor_sync(full, hi16 ? s1 : s3, 16);
                float v2 = (hi16 ? s3 : s1) + rB;
                float rC = __shfl_xor_sync(full, hi8 ? u2 : v2, 8);
                float w  = (hi8 ? v2 : u2) + rC;
                w += __shfl_xor_sync(full, w, 4);
                w += __shfl_xor_sync(full, w, 2);
                w += __shfl_xor_sync(full, w, 1);
                if ((lane & 7) == 0) {
                    const int su = u - oxk, sv = vv - oyk;
                    if (((unsigned)su < 10u) & ((unsigned)sv < 10u))
                        Cs[warp][k8][sv * 10 + su] = w;
                }
                u++; if (u == S) { u = 0; vv++; }
            }
            __syncwarp();

            // bilinear combine: 4 points x 81 outputs
            for (int t2 = lane; t2 < 4 * SIDE * SIDE; t2 += 32) {
                const int pp = t2 / 81;
                const int r  = t2 - pp * 81;
                const int i2 = r / 9;       // x-offset index
                const int j2 = r % 9;       // y-offset index
                const float wx0 = pp == 0 ? wx0r[0] : pp == 1 ? wx0r[1] : pp == 2 ? wx0r[2] : wx0r[3];
                const float wx1 = pp == 0 ? wx1r[0] : pp == 1 ? wx1r[1] : pp == 2 ? wx1r[2] : wx1r[3];
                const float wy0 = pp == 0 ? wy0r[0] : pp == 1 ? wy0r[1] : pp == 2 ? wy0r[2] : wy0r[3];
                const float wy1 = pp == 0 ? wy1r[0] : pp == 1 ? wy1r[1] : pp == 2 ? wy1r[2] : wy1r[3];
                const float* C = Cs[warp][pp];
                const float val = wy0 * (wx0 * C[j2 * 10 + i2] + wx1 * C[j2 * 10 + i2 + 1])
                                + wy1 * (wx0 * C[(j2 + 1) * 10 + i2] + wx1 * C[(j2 + 1) * 10 + i2 + 1]);
                if (pp < npts)
                    tmp[(size_t)(g0 + pp) * OUTCH + lvl * (SIDE * SIDE) + r] = val;
            }
            __syncwarp();
        }
    }
}

// ---------------------------------------------------------------------------
// Kernel C: unpermute staged output [pos][324] -> final (B, 324, M).
// Coalesced writes; scattered 4B reads (hidden by MLP, L2-resident).
// ---------------------------------------------------------------------------
__global__ void unpermute_kernel(float* __restrict__ out) {
    int tid = blockIdx.x * blockDim.x + threadIdx.x;   // over B*OUTCH*MM
    if (tid >= BB * OUTCH * MM) return;
    const int m  = tid & (MM - 1);
    const int ch = (tid >> 12) % OUTCH;
    const int b  = tid / (OUTCH * MM);
    const int pos = g_ipos[b * MM + m];
    out[tid] = __ldg(&g_tmp[(size_t)pos * OUTCH + ch]);
}

// ---------------------------------------------------------------------------
extern "C" void kernel_launch(void* const* d_in, const int* in_sizes, int n_in,
                              void* d_out, int out_size) {
    const float* fmap1 = (const float*)d_in[0];   // (B, M, C)
    const float* fmap2 = (const float*)d_in[1];   // (B, C, H, W)
    const float* cents = (const float*)d_in[2];   // (B, M, 2)
    float* out = (float*)d_out;                   // (B, 324, M)

    // Level 0: transpose to pixel-major
    {
        dim3 grid(HH * WW / 32, CC / 32, BB);
        dim3 block(32, 8);
        transpose_l0_kernel<<<grid, block>>>(fmap2);
    }
    // Levels 1..3: fused pooling from level 0 (one launch)
    {
        int tot = BB * (32 * 32 + 16 * 16 + 8 * 8) * CC;
        pool_fused_kernel<<<(tot + 255) / 256, 256>>>();
    }
    // Spatial counting sort (single block)
    sort_kernel<<<1, 1024>>>(cents);
    // Fused correlation + bilinear sampling: block per bin, warp per 4 points
    {
        float* tmp;
        cudaGetSymbolAddress((void**)&tmp, g_tmp);
        sample_kernel<<<512, 256>>>(fmap1, cents, tmp);
    }
    // Unpermute to final layout
    {
        int tot = BB * OUTCH * MM;
        unpermute_kernel<<<(tot + 255) / 256, 256>>>(out);
    }
}

// round 8
// speedup vs baseline: 1.0947x; 1.0947x over previous
#include <cuda_runtime.h>
#include <cuda_bf16.h>
#include <cstdint>

typedef unsigned long long ull;

// Problem constants
#define BB 2
#define MM 4096
#define CC 256
#define HH 64
#define WW 64
#define NLVL 4
#define RAD 4
#define SIDE 9
#define OUTCH (NLVL * SIDE * SIDE)   // 324

// Pyramid (pixel-major: [b][level][y][x][c]) in float
#define OFF0 0
#define OFF1 (4096 * 256)
#define OFF2 ((4096 + 1024) * 256)
#define OFF3 ((4096 + 1024 + 256) * 256)
#define BSTR ((4096 + 1024 + 256 + 64) * 256)
#define PYR_TOTAL (BB * BSTR)

__device__ float4 g_pyr4[PYR_TOTAL / 4];     // 11.1 MB static scratch
__device__ int g_binCnt[512];
__device__ int g_binStart[512];
__device__ int g_perm[BB * MM];              // sorted position -> point id
__device__ int g_ipos[BB * MM];              // point id -> sorted position
__device__ float g_tmp[BB * MM * OUTCH];     // staged output, [pos][324]

// ---------------------------------------------------------------------------
// packed f32x2 helpers
// ---------------------------------------------------------------------------
__device__ __forceinline__ ull pk(float x, float y) {
    ull r;
    asm("mov.b64 %0, {%1, %2};" : "=l"(r) : "f"(x), "f"(y));
    return r;
}
__device__ __forceinline__ float2 upk(ull v) {
    float2 f;
    asm("mov.b64 {%0, %1}, %2;" : "=f"(f.x), "=f"(f.y) : "l"(v));
    return f;
}
__device__ __forceinline__ void ffma2(ull& acc, ull a, ull b) {
    asm("fma.rn.f32x2 %0, %1, %2, %3;" : "=l"(acc) : "l"(a), "l"(b), "l"(acc));
}

// ---------------------------------------------------------------------------
// Kernel A1: transpose fmap2 (b, c, p) -> pyramid level 0 (b, p, c)
// ---------------------------------------------------------------------------
__global__ void transpose_l0_kernel(const float* __restrict__ fmap2) {
    __shared__ float tile[32][33];
    float* g = reinterpret_cast<float*>(g_pyr4);
    int b  = blockIdx.z;
    int c0 = blockIdx.y * 32;
    int p0 = blockIdx.x * 32;
    const float* in_b = fmap2 + (size_t)b * CC * (HH * WW);
    #pragma unroll
    for (int r = threadIdx.y; r < 32; r += 8)
        tile[r][threadIdx.x] = in_b[(size_t)(c0 + r) * (HH * WW) + p0 + threadIdx.x];
    __syncthreads();
    float* out_b = g + (size_t)b * BSTR;
    #pragma unroll
    for (int r = threadIdx.y; r < 32; r += 8)
        out_b[(size_t)(p0 + r) * CC + c0 + threadIdx.x] = tile[threadIdx.x][r];
}

// ---------------------------------------------------------------------------
// Kernel A2 (fused): levels 1..3 pooled directly from level 0 (one launch).
// ---------------------------------------------------------------------------
__global__ void pool_fused_kernel() {
    float* g = reinterpret_cast<float*>(g_pyr4);
    const int n1 = BB * 32 * 32 * CC;
    const int n2 = BB * 16 * 16 * CC;
    const int n3 = BB * 8 * 8 * CC;
    int tid = blockIdx.x * blockDim.x + threadIdx.x;
    int Wo, k, off, local;
    float inv;
    if (tid < n1)            { Wo = 32; k = 2; off = OFF1; local = tid;           inv = 0.25f; }
    else if (tid < n1 + n2)  { Wo = 16; k = 4; off = OFF2; local = tid - n1;      inv = 1.f / 16.f; }
    else if (tid < n1+n2+n3) { Wo = 8;  k = 8; off = OFF3; local = tid - n1 - n2; inv = 1.f / 64.f; }
    else return;
    int c = local & (CC - 1);
    int idx = local >> 8;
    int x = idx % Wo; idx /= Wo;
    int y = idx % Wo; idx /= Wo;
    int b = idx;
    const float* ib = g + (size_t)b * BSTR;   // level 0
    float s = 0.0f;
    for (int dy = 0; dy < k; dy++)
        for (int dx = 0; dx < k; dx++)
            s += ib[((size_t)(y * k + dy) * WW + (x * k + dx)) * CC + c];
    g[(size_t)b * BSTR + off + ((size_t)y * Wo + x) * CC + c] = s * inv;
}

// ---------------------------------------------------------------------------
// Kernel S: single-block counting sort into 4x4-pixel bins (512 bins total)
// ---------------------------------------------------------------------------
__global__ void sort_kernel(const float* __restrict__ cents) {
    __shared__ int cnt[512];
    __shared__ int off[512];
    __shared__ int s[512];
    const int t = threadIdx.x;          // 1024 threads
    if (t < 512) cnt[t] = 0;
    __syncthreads();
    int mybin[8];
    #pragma unroll
    for (int i = 0; i < 8; i++) {
        int pt = t + i * 1024;
        float cx = cents[(size_t)pt * 2 + 0];
        float cy = cents[(size_t)pt * 2 + 1];
        int bx = min(15, ((int)cx) >> 2);
        int by = min(15, ((int)cy) >> 2);
        int bin = ((pt >> 12) << 8) | (by << 4) | bx;
        mybin[i] = bin;
        atomicAdd(&cnt[bin], 1);
    }
    __syncthreads();
    if (t < 512) s[t] = cnt[t];
    __syncthreads();
    #pragma unroll
    for (int d = 1; d < 512; d <<= 1) {
        int add = 0;
        if (t < 512 && t >= d) add = s[t - d];
        __syncthreads();
        if (t < 512) s[t] += add;
        __syncthreads();
    }
    if (t < 512) {
        int st = s[t] - cnt[t];
        off[t] = st;
        g_binStart[t] = st;
        g_binCnt[t] = cnt[t];
    }
    __syncthreads();
    #pragma unroll
    for (int i = 0; i < 8; i++) {
        int pt = t + i * 1024;
        int pos = atomicAdd(&off[mybin[i]], 1);
        g_perm[pos] = pt;
        g_ipos[pt] = pos;
    }
}

// ---------------------------------------------------------------------------
// Kernel B: block per bin (128 threads), warp per PAIR of same-bin points.
// Each pixel of the pair's shared superset window (<=13 per axis) is loaded
// once and dotted against both queries: ~1.7x fewer LDG than warp-per-point.
// 2 pixels in flight per iteration (MLP), 4 reduce values per 6-shfl block.
// ---------------------------------------------------------------------------
__global__ void __launch_bounds__(128)
sample_kernel(const float* __restrict__ fmap1,
              const float* __restrict__ cents,
              float* __restrict__ tmp) {
    __shared__ float Cs[4][2][100];
    const int bin = blockIdx.x;
    const int cnt = g_binCnt[bin];
    if (cnt == 0) return;
    const int start = g_binStart[bin];
    const int b = bin >> 8;
    const int warp = threadIdx.x >> 5;
    const int lane = threadIdx.x & 31;
    const float* pyr = reinterpret_cast<const float*>(g_pyr4) + (size_t)b * BSTR;

    const int nIter = (cnt + 7) >> 3;          // 8 points per block-iteration
    for (int it = 0; it < nIter; it++) {
        const int g0 = start + it * 8 + warp * 2;
        const int rem = start + cnt - g0;
        const bool active = rem > 0;
        const int npts = active ? (rem > 1 ? 2 : 1) : 0;

        ull qA0 = 0, qB0 = 0, qC0 = 0, qD0 = 0;
        ull qA1 = 0, qB1 = 0, qC1 = 0, qD1 = 0;
        float cx0 = 0.f, cy0 = 0.f, cx1 = 0.f, cy1 = 0.f;
        if (active) {
            const int ptA = g_perm[g0];
            const int ptB = g_perm[g0 + (npts - 1)];   // replicate if single
            const float4* qp = reinterpret_cast<const float4*>(fmap1 + (size_t)ptA * CC);
            const float4 a0 = qp[lane], a1 = qp[lane + 32];
            qA0 = pk(a0.x, a0.y); qB0 = pk(a0.z, a0.w);
            qC0 = pk(a1.x, a1.y); qD0 = pk(a1.z, a1.w);
            const float4* qq = reinterpret_cast<const float4*>(fmap1 + (size_t)ptB * CC);
            const float4 b0 = qq[lane], b1 = qq[lane + 32];
            qA1 = pk(b0.x, b0.y); qB1 = pk(b0.z, b0.w);
            qC1 = pk(b1.x, b1.y); qD1 = pk(b1.z, b1.w);
            cx0 = cents[(size_t)ptA * 2 + 0]; cy0 = cents[(size_t)ptA * 2 + 1];
            cx1 = cents[(size_t)ptB * 2 + 0]; cy1 = cents[(size_t)ptB * 2 + 1];
        }

        #pragma unroll
        for (int lvl = 0; lvl < NLVL; lvl++) {
            __syncthreads();               // lockstep warps on the shared bin patch
            if (active) {
                const int W = (lvl == 0) ? 64 : (lvl == 1) ? 32 : (lvl == 2) ? 16 : 8;
                const int lOff = (lvl == 0) ? OFF0 : (lvl == 1) ? OFF1 : (lvl == 2) ? OFF2 : OFF3;
                const float sc = 1.0f / (float)(1 << lvl);

                const float cxl0 = cx0 * sc, cyl0 = cy0 * sc;
                const float cxl1 = cx1 * sc, cyl1 = cy1 * sc;
                const float fxA = floorf(cxl0), fyA = floorf(cyl0);
                const float fxB = floorf(cxl1), fyB = floorf(cyl1);
                const float wxA1 = cxl0 - fxA, wxA0 = 1.0f - wxA1;
                const float wyA1 = cyl0 - fyA, wyA0 = 1.0f - wyA1;
                const float wxB1 = cxl1 - fxB, wxB0 = 1.0f - wxB1;
                const float wyB1 = cyl1 - fyB, wyB0 = 1.0f - wyB1;
                const int ax0 = (int)fxA, ay0 = (int)fyA;
                const int ax1 = (int)fxB, ay1 = (int)fyB;
                const int ix0 = min(ax0, ax1) - 4;
                const int iy0 = min(ay0, ay1) - 4;
                const int Sx = max(ax0, ax1) - min(ax0, ax1) + 10;   // <= 13
                const int Sy = max(ay0, ay1) - min(ay0, ay1) + 10;
                const int dx0 = ax0 - 4 - ix0, dy0 = ay0 - 4 - iy0;  // 0..3
                const int dx1 = ax1 - 4 - ix0, dy1 = ay1 - 4 - iy0;

                // scatter designation for lanes 0,8,16,24:
                //   li = lane>>3: 0 -> (pix0,pt0), 1 -> (pix0,pt1),
                //                 2 -> (pix1,pt0), 3 -> (pix1,pt1)
                const int li = lane >> 3;
                const int lpt = li & 1;
                const int dxk = lpt ? dx1 : dx0;
                const int dyk = lpt ? dy1 : dy0;

                const float4* base4 = reinterpret_cast<const float4*>(pyr + lOff);
                const int npix = Sx * Sy;
                int u0 = 0, v0 = 0;
                for (int p = 0; p < npix; p += 2) {
                    int u1p = u0 + 1, v1p = v0;
                    if (u1p == Sx) { u1p = 0; v1p++; }
                    const int x0 = ix0 + u0, y0 = iy0 + v0;
                    const int x1 = ix0 + u1p, y1 = iy0 + v1p;
                    const bool ok0 = ((unsigned)x0 < (unsigned)W) & ((unsigned)y0 < (unsigned)W);
                    const bool ok1 = (p + 1 < npix) &
                                     ((unsigned)x1 < (unsigned)W) & ((unsigned)y1 < (unsigned)W);
                    float s00 = 0.f, s01 = 0.f, s10 = 0.f, s11 = 0.f;
                    // two independent pixel chains -> MLP 2
                    if (ok0) {
                        const float4* f = base4 + (size_t)(y0 * W + x0) * 64;
                        const float4 A = f[lane], Bv = f[lane + 32];
                        const ull pA = pk(A.x, A.y),   pB = pk(A.z, A.w);
                        const ull pC = pk(Bv.x, Bv.y), pD = pk(Bv.z, Bv.w);
                        ull a = pk(0.f, 0.f), c = pk(0.f, 0.f);
                        ffma2(a, pA, qA0); ffma2(a, pB, qB0); ffma2(a, pC, qC0); ffma2(a, pD, qD0);
                        ffma2(c, pA, qA1); ffma2(c, pB, qB1); ffma2(c, pC, qC1); ffma2(c, pD, qD1);
                        const float2 t0 = upk(a); s00 = t0.x + t0.y;
                        const float2 t1 = upk(c); s01 = t1.x + t1.y;
                    }
                    if (ok1) {
                        const float4* f = base4 + (size_t)(y1 * W + x1) * 64;
                        const float4 A = f[lane], Bv = f[lane + 32];
                        const ull pA = pk(A.x, A.y),   pB = pk(A.z, A.w);
                        const ull pC = pk(Bv.x, Bv.y), pD = pk(Bv.z, Bv.w);
                        ull a = pk(0.f, 0.f), c = pk(0.f, 0.f);
                        ffma2(a, pA, qA0); ffma2(a, pB, qB0); ffma2(a, pC, qC0); ffma2(a, pD, qD0);
                        ffma2(c, pA, qA1); ffma2(c, pB, qB1); ffma2(c, pC, qC1); ffma2(c, pD, qD1);
                        const float2 t0 = upk(a); s10 = t0.x + t0.y;
                        const float2 t1 = upk(c); s11 = t1.x + t1.y;
                    }
                    // 4-value reduction: lanes 0-7 -> s00, 8-15 -> s01,
                    //                    16-23 -> s10, 24-31 -> s11
                    const unsigned full = 0xffffffffu;
                    const bool hi16 = (lane & 16) != 0;
                    const bool hi8  = (lane & 8) != 0;
                    float rA = __shfl_xor_sync(full, hi16 ? s00 : s10, 16);
                    float u2 = (hi16 ? s10 : s00) + rA;
                    float rB = __shfl_xor_sync(full, hi16 ? s01 : s11, 16);
                    float v2 = (hi16 ? s11 : s01) + rB;
                    float rC = __shfl_xor_sync(full, hi8 ? u2 : v2, 8);
                    float w  = (hi8 ? v2 : u2) + rC;
                    w += __shfl_xor_sync(full, w, 4);
                    w += __shfl_xor_sync(full, w, 2);
                    w += __shfl_xor_sync(full, w, 1);
                    if ((lane & 7) == 0) {
                        const int uu  = (li >> 1) ? u1p : u0;
                        const int vvv = (li >> 1) ? v1p : v0;
                        const int su = uu - dxk, sv = vvv - dyk;
                        if (((unsigned)su < 10u) & ((unsigned)sv < 10u))
                            Cs[warp][lpt][sv * 10 + su] = w;
                    }
                    u0 = u1p + 1; v0 = v1p;
                    if (u0 == Sx) { u0 = 0; v0++; }
                }
                __syncwarp();

                // bilinear combine: 2 points x 81 outputs
                for (int t2 = lane; t2 < 2 * SIDE * SIDE; t2 += 32) {
                    const int pp = (t2 >= 81) ? 1 : 0;
                    const int r = t2 - pp * 81;
                    const int i2 = r / 9;   // x-offset index
                    const int j2 = r % 9;   // y-offset index
                    const float wx0 = pp ? wxB0 : wxA0;
                    const float wx1 = pp ? wxB1 : wxA1;
                    const float wy0 = pp ? wyB0 : wyA0;
                    const float wy1 = pp ? wyB1 : wyA1;
                    const float* C = Cs[warp][pp];
                    const float val =
                        wy0 * (wx0 * C[j2 * 10 + i2] + wx1 * C[j2 * 10 + i2 + 1]) +
                        wy1 * (wx0 * C[(j2 + 1) * 10 + i2] + wx1 * C[(j2 + 1) * 10 + i2 + 1]);
                    if (pp < npts)
                        tmp[(size_t)(g0 + pp) * OUTCH + lvl * (SIDE * SIDE) + r] = val;
                }
                __syncwarp();
            }
        }
    }
}

// ---------------------------------------------------------------------------
// Kernel C: unpermute staged output [pos][324] -> final (B, 324, M)
// ---------------------------------------------------------------------------
__global__ void unpermute_kernel(float* __restrict__ out) {
    int tid = blockIdx.x * blockDim.x + threadIdx.x;   // over B*OUTCH*MM
    if (tid >= BB * OUTCH * MM) return;
    const int m  = tid & (MM - 1);
    const int ch = (tid >> 12) % OUTCH;
    const int b  = tid / (OUTCH * MM);
    const int pos = g_ipos[b * MM + m];
    out[tid] = __ldg(&g_tmp[(size_t)pos * OUTCH + ch]);
}

// ---------------------------------------------------------------------------
extern "C" void kernel_launch(void* const* d_in, const int* in_sizes, int n_in,
                              void* d_out, int out_size) {
    const float* fmap1 = (const float*)d_in[0];   // (B, M, C)
    const float* fmap2 = (const float*)d_in[1];   // (B, C, H, W)
    const float* cents = (const float*)d_in[2];   // (B, M, 2)
    float* out = (float*)d_out;                   // (B, 324, M)

    // Level 0: transpose to pixel-major
    {
        dim3 grid(HH * WW / 32, CC / 32, BB);
        dim3 block(32, 8);
        transpose_l0_kernel<<<grid, block>>>(fmap2);
    }
    // Levels 1..3: fused pooling from level 0 (one launch)
    {
        int tot = BB * (32 * 32 + 16 * 16 + 8 * 8) * CC;
        pool_fused_kernel<<<(tot + 255) / 256, 256>>>();
    }
    // Spatial counting sort (single block)
    sort_kernel<<<1, 1024>>>(cents);
    // Fused correlation + bilinear sampling: block per bin, warp per 2 points
    {
        float* tmp;
        cudaGetSymbolAddress((void**)&tmp, g_tmp);
        sample_kernel<<<512, 128>>>(fmap1, cents, tmp);
    }
    // Unpermute to final layout
    {
        int tot = BB * OUTCH * MM;
        unpermute_kernel<<<(tot + 255) / 256, 256>>>(out);
    }
}